// round 13
// baseline (speedup 1.0000x reference)
#include <cuda_runtime.h>
#include <cuda_fp16.h>
#include <cstdint>

// RNN_49684181680264 : Elman RNN forward, B=16384, T=1024, H=32.
//   h_t = tanh(h_{t-1} @ Whh + b_hh + x_t * Wxh + b_xh);  out = h_T @ Wout + b_out
//
// R13: R12 profile showed 0.865 warps/SMSP with issue=22.6% -- the wall is
// exposed dependency stalls on a lone warp per scheduler. Occupancy is capped
// (1024 16-row tiles max), so fill the stalls INSIDE the warp: TILES=4
// (64 rows/warp, 256 CTAs) = 16 independent dependency streams (4 tiles x
// 4 n-tile chains). Per-tile math identical to R12 (f16 W single-pass,
// 8 HMMA/tile, f32 MUFU.TANH, CVT repack; rel_err 3.46e-4 measured).
// th[] array dropped: epilogue reads h from the f16 A-fragments directly
// (saves ~32 regs; h is already f16-quantized every step anyway).

#define RNN_T 1024
#define RNN_H 32
#define TILES 4
#define ROWS_PER_CTA (16 * TILES)
#define TT 32

typedef uint32_t u32;

__device__ __forceinline__ u32 pack_half2(float v0, float v1) {
    u32 d;
    asm("cvt.rn.f16x2.f32 %0, %1, %2;" : "=r"(d) : "f"(v1), "f"(v0));
    return d;
}
__device__ __forceinline__ void mma16816(float d[4], const u32 a[4], u32 b0, u32 b1) {
    asm volatile(
        "mma.sync.aligned.m16n8k16.row.col.f32.f16.f16.f32 "
        "{%0,%1,%2,%3}, {%4,%5,%6,%7}, {%8,%9}, {%0,%1,%2,%3};"
        : "+f"(d[0]), "+f"(d[1]), "+f"(d[2]), "+f"(d[3])
        : "r"(a[0]), "r"(a[1]), "r"(a[2]), "r"(a[3]), "r"(b0), "r"(b1));
}
__device__ __forceinline__ float tanh_mufu(float v) {
    float t;
    asm("tanh.approx.f32 %0, %1;" : "=f"(t) : "f"(v));
    return t;
}

__global__ __launch_bounds__(32)
void rnn_mma_kernel(const float* __restrict__ x,
                    const float* __restrict__ Wxh,
                    const float* __restrict__ b_xh,
                    const float* __restrict__ Whh,
                    const float* __restrict__ b_hh,
                    const float* __restrict__ Wout,
                    const float* __restrict__ b_out,
                    float* __restrict__ out)
{
    __shared__ float sX[ROWS_PER_CTA][TT + 1];

    const int lane = threadIdx.x;
    const int b0   = blockIdx.x * ROWS_PER_CTA;
    const int qr   = lane >> 2;
    const int qc   = (lane & 3) * 2;

    // ---- B fragments: W as round-to-nearest f16, register-resident ----
    u32 Bh[4][2][2];
    #pragma unroll
    for (int j = 0; j < 4; j++)
        #pragma unroll
        for (int kt = 0; kt < 2; kt++)
            #pragma unroll
            for (int r = 0; r < 2; r++) {
                int n = 8 * j + qr;
                int k = 16 * kt + 8 * r + qc;
                Bh[j][kt][r] = pack_half2(Whh[k * RNN_H + n],
                                          Whh[(k + 1) * RNN_H + n]);
            }

    // ---- per-thread column constants ----
    float wxh[8], bs[8], wo[8];
    #pragma unroll
    for (int j = 0; j < 4; j++)
        #pragma unroll
        for (int e = 0; e < 2; e++) {
            int c = 8 * j + qc + e;
            wxh[2 * j + e] = Wxh[c];
            bs[2 * j + e]  = b_xh[c] + b_hh[c];
            wo[2 * j + e]  = Wout[c];
        }

    // ---- A fragments per tile (h as f16), h = 0 ----
    // Ahi[u][kt][r] holds pair (h[4j+e], h[4j+e+1]) with j=2kt+(r>>1),
    // e=(r&1)*2; elements (0,1) -> row qr, (2,3) -> row qr+8 of tile u.
    u32 Ahi[TILES][2][4];
    #pragma unroll
    for (int u = 0; u < TILES; u++)
        #pragma unroll
        for (int kt = 0; kt < 2; kt++)
            #pragma unroll
            for (int r = 0; r < 4; r++) Ahi[u][kt][r] = 0u;

    for (int t0 = 0; t0 < RNN_T; t0 += TT) {
        __syncwarp();
        #pragma unroll
        for (int i = lane; i < ROWS_PER_CTA * TT; i += 32) {
            int r = i >> 5, c = i & 31;
            sX[r][c] = x[(size_t)(b0 + r) * RNN_T + t0 + c];
        }
        __syncwarp();

        #pragma unroll 1
        for (int tt = 0; tt < TT; tt++) {
            float D[TILES][4][4];

            // seeds: D = bias + x*Wxh  (independent per tile)
            #pragma unroll
            for (int u = 0; u < TILES; u++) {
                float xv0 = sX[16 * u + qr][tt];
                float xv1 = sX[16 * u + qr + 8][tt];
                #pragma unroll
                for (int j = 0; j < 4; j++) {
                    D[u][j][0] = fmaf(xv0, wxh[2 * j],     bs[2 * j]);
                    D[u][j][1] = fmaf(xv0, wxh[2 * j + 1], bs[2 * j + 1]);
                    D[u][j][2] = fmaf(xv1, wxh[2 * j],     bs[2 * j]);
                    D[u][j][3] = fmaf(xv1, wxh[2 * j + 1], bs[2 * j + 1]);
                }
            }

            // 8 HMMA per tile, tiles interleaved (16 independent chains)
            #pragma unroll
            for (int j = 0; j < 4; j++)
                #pragma unroll
                for (int u = 0; u < TILES; u++) {
                    mma16816(D[u][j], Ahi[u][0], Bh[j][0][0], Bh[j][0][1]);
                    mma16816(D[u][j], Ahi[u][1], Bh[j][1][0], Bh[j][1][1]);
                }

            // h = tanh(D) (f32 MUFU) -> pack straight into A fragments
            #pragma unroll
            for (int u = 0; u < TILES; u++)
                #pragma unroll
                for (int kt = 0; kt < 2; kt++)
                    #pragma unroll
                    for (int r = 0; r < 4; r++) {
                        int j = 2 * kt + (r >> 1);
                        int e = (r & 1) * 2;
                        Ahi[u][kt][r] = pack_half2(tanh_mufu(D[u][j][e]),
                                                   tanh_mufu(D[u][j][e + 1]));
                    }
        }
    }

    // ---- epilogue: out[b] = h . Wout + b_out, h read from A fragments ----
    #pragma unroll
    for (int u = 0; u < TILES; u++) {
        float po0 = 0.0f, po1 = 0.0f;
        #pragma unroll
        for (int kt = 0; kt < 2; kt++)
            #pragma unroll
            for (int r = 0; r < 4; r++) {
                int j = 2 * kt + (r >> 1);
                int e = (r & 1) * 2;
                __half2 h2 = *reinterpret_cast<const __half2*>(&Ahi[u][kt][r]);
                float v0 = __low2float(h2);
                float v1 = __high2float(h2);
                if (e == 0) {   // rows qr
                    po0 = fmaf(v0, wo[2 * j],     po0);
                    po0 = fmaf(v1, wo[2 * j + 1], po0);
                } else {        // rows qr+8
                    po1 = fmaf(v0, wo[2 * j],     po1);
                    po1 = fmaf(v1, wo[2 * j + 1], po1);
                }
            }
        po0 += __shfl_xor_sync(0xFFFFFFFFu, po0, 1);
        po0 += __shfl_xor_sync(0xFFFFFFFFu, po0, 2);
        po1 += __shfl_xor_sync(0xFFFFFFFFu, po1, 1);
        po1 += __shfl_xor_sync(0xFFFFFFFFu, po1, 2);
        if ((lane & 3) == 0) {
            float bo = b_out[0];
            out[b0 + 16 * u + qr]     = po0 + bo;
            out[b0 + 16 * u + qr + 8] = po1 + bo;
        }
    }
}

extern "C" void kernel_launch(void* const* d_in, const int* in_sizes, int n_in,
                              void* d_out, int out_size)
{
    const float* x     = (const float*)d_in[0];
    const float* Wxh   = (const float*)d_in[1];
    const float* b_xh  = (const float*)d_in[2];
    const float* Whh   = (const float*)d_in[3];
    const float* b_hh  = (const float*)d_in[4];
    const float* Wout  = (const float*)d_in[5];
    const float* b_out = (const float*)d_in[6];
    float* out = (float*)d_out;

    dim3 grid(16384 / ROWS_PER_CTA);   // 256 CTAs, one warp, four tiles each
    dim3 blk(32);
    rnn_mma_kernel<<<grid, blk>>>(x, Wxh, b_xh, Whh, b_hh, Wout, b_out, out);
}

// round 14
// speedup vs baseline: 2.4544x; 2.4544x over previous
#include <cuda_runtime.h>
#include <cuda_fp16.h>
#include <cstdint>

// RNN_49684181680264 : Elman RNN forward, B=16384, T=1024, H=32.
//   h_t = tanh(h_{t-1} @ Whh + b_hh + x_t * Wxh + b_xh);  out = h_T @ Wout + b_out
//
// R14: SMSP-spread experiment. All configs since R8 used 1-warp CTAs; warps
// map to SMSPs by wid%4 WITHIN a CTA, so co-resident single-warp CTAs may all
// crowd SMSP 0 (3 of 4 schedulers idle) -- which would explain the invariant
// ~530cyc/step wall and issue=22%. This round: 256 CTAs x 4 warps (128 thr),
// warp w owns tile blockIdx*4+w -> wid spans 0..3, all SMSPs provably used;
// 1024 warps = 1.73/SMSP evenly. Per-tile math is EXACTLY R12's proven body
// (f16 W single-pass, 8 HMMA/tile in two 2-deep chains, f32 MUFU.TANH, CVT
// repack; 236us / rel_err 3.46e-4).

#define RNN_T 1024
#define RNN_H 32
#define WARPS 4
#define ROWS_PER_CTA (16 * WARPS)
#define TT 32

typedef uint32_t u32;

__device__ __forceinline__ u32 pack_half2(float v0, float v1) {
    u32 d;
    asm("cvt.rn.f16x2.f32 %0, %1, %2;" : "=r"(d) : "f"(v1), "f"(v0));
    return d;
}
__device__ __forceinline__ void mma16816(float d[4], const u32 a[4], u32 b0, u32 b1) {
    asm volatile(
        "mma.sync.aligned.m16n8k16.row.col.f32.f16.f16.f32 "
        "{%0,%1,%2,%3}, {%4,%5,%6,%7}, {%8,%9}, {%0,%1,%2,%3};"
        : "+f"(d[0]), "+f"(d[1]), "+f"(d[2]), "+f"(d[3])
        : "r"(a[0]), "r"(a[1]), "r"(a[2]), "r"(a[3]), "r"(b0), "r"(b1));
}
__device__ __forceinline__ float tanh_mufu(float v) {
    float t;
    asm("tanh.approx.f32 %0, %1;" : "=f"(t) : "f"(v));
    return t;
}

__global__ __launch_bounds__(128)
void rnn_mma_kernel(const float* __restrict__ x,
                    const float* __restrict__ Wxh,
                    const float* __restrict__ b_xh,
                    const float* __restrict__ Whh,
                    const float* __restrict__ b_hh,
                    const float* __restrict__ Wout,
                    const float* __restrict__ b_out,
                    float* __restrict__ out)
{
    __shared__ float sX[ROWS_PER_CTA][TT + 1];

    const int tid  = threadIdx.x;
    const int lane = tid & 31;
    const int wid  = tid >> 5;          // warp -> SMSP wid%4: all 4 SMSPs used
    const int row0 = wid * 16;          // my tile's rows within the CTA
    const int b0   = blockIdx.x * ROWS_PER_CTA;
    const int qr   = lane >> 2;
    const int qc   = (lane & 3) * 2;

    // ---- B fragments: W as round-to-nearest f16, register-resident ----
    u32 Bh[4][2][2];
    #pragma unroll
    for (int j = 0; j < 4; j++)
        #pragma unroll
        for (int kt = 0; kt < 2; kt++)
            #pragma unroll
            for (int r = 0; r < 2; r++) {
                int n = 8 * j + qr;
                int k = 16 * kt + 8 * r + qc;
                Bh[j][kt][r] = pack_half2(Whh[k * RNN_H + n],
                                          Whh[(k + 1) * RNN_H + n]);
            }

    // ---- per-thread column constants ----
    float wxh[8], bs[8], wo[8];
    #pragma unroll
    for (int j = 0; j < 4; j++)
        #pragma unroll
        for (int e = 0; e < 2; e++) {
            int c = 8 * j + qc + e;
            wxh[2 * j + e] = Wxh[c];
            bs[2 * j + e]  = b_xh[c] + b_hh[c];
            wo[2 * j + e]  = Wout[c];
        }

    // ---- A fragments (h as f16), h = 0 ----
    u32 Ahi[2][4];
    #pragma unroll
    for (int kt = 0; kt < 2; kt++)
        #pragma unroll
        for (int r = 0; r < 4; r++) Ahi[kt][r] = 0u;

    float th[16];

    for (int t0 = 0; t0 < RNN_T; t0 += TT) {
        __syncthreads();
        // stage x for all 64 rows of the CTA, coalesced along t
        #pragma unroll
        for (int i = tid; i < ROWS_PER_CTA * TT; i += 128) {
            int r = i >> 5, c = i & 31;
            sX[r][c] = x[(size_t)(b0 + r) * RNN_T + t0 + c];
        }
        __syncthreads();

        #pragma unroll 1
        for (int tt = 0; tt < TT; tt++) {
            float xv0 = sX[row0 + qr][tt];
            float xv1 = sX[row0 + qr + 8][tt];

            // seeds: D = bias + x*Wxh
            float D[4][4];
            #pragma unroll
            for (int j = 0; j < 4; j++) {
                D[j][0] = fmaf(xv0, wxh[2 * j],     bs[2 * j]);
                D[j][1] = fmaf(xv0, wxh[2 * j + 1], bs[2 * j + 1]);
                D[j][2] = fmaf(xv1, wxh[2 * j],     bs[2 * j]);
                D[j][3] = fmaf(xv1, wxh[2 * j + 1], bs[2 * j + 1]);
            }

            // 8 HMMA: 4 n-tiles x 2-deep kt chain
            #pragma unroll
            for (int j = 0; j < 4; j++) {
                mma16816(D[j], Ahi[0], Bh[j][0][0], Bh[j][0][1]);
                mma16816(D[j], Ahi[1], Bh[j][1][0], Bh[j][1][1]);
            }

            // h = tanh(D), f32 MUFU; repack to A fragments (layout closure)
            #pragma unroll
            for (int j = 0; j < 4; j++) {
                th[4 * j]     = tanh_mufu(D[j][0]);
                th[4 * j + 1] = tanh_mufu(D[j][1]);
                th[4 * j + 2] = tanh_mufu(D[j][2]);
                th[4 * j + 3] = tanh_mufu(D[j][3]);
            }
            #pragma unroll
            for (int kt = 0; kt < 2; kt++)
                #pragma unroll
                for (int r = 0; r < 4; r++) {
                    int j = 2 * kt + (r >> 1);
                    int e = (r & 1) * 2;
                    Ahi[kt][r] = pack_half2(th[4 * j + e], th[4 * j + e + 1]);
                }
        }
    }

    // ---- epilogue: out[b] = h . Wout + b_out ----
    float po0 = 0.0f, po1 = 0.0f;
    #pragma unroll
    for (int j = 0; j < 4; j++) {
        po0 = fmaf(th[4 * j],     wo[2 * j],     po0);
        po0 = fmaf(th[4 * j + 1], wo[2 * j + 1], po0);
        po1 = fmaf(th[4 * j + 2], wo[2 * j],     po1);
        po1 = fmaf(th[4 * j + 3], wo[2 * j + 1], po1);
    }
    po0 += __shfl_xor_sync(0xFFFFFFFFu, po0, 1);
    po0 += __shfl_xor_sync(0xFFFFFFFFu, po0, 2);
    po1 += __shfl_xor_sync(0xFFFFFFFFu, po1, 1);
    po1 += __shfl_xor_sync(0xFFFFFFFFu, po1, 2);
    if ((lane & 3) == 0) {
        float bo = b_out[0];
        out[b0 + row0 + qr]     = po0 + bo;
        out[b0 + row0 + qr + 8] = po1 + bo;
    }
}

extern "C" void kernel_launch(void* const* d_in, const int* in_sizes, int n_in,
                              void* d_out, int out_size)
{
    const float* x     = (const float*)d_in[0];
    const float* Wxh   = (const float*)d_in[1];
    const float* b_xh  = (const float*)d_in[2];
    const float* Whh   = (const float*)d_in[3];
    const float* b_hh  = (const float*)d_in[4];
    const float* Wout  = (const float*)d_in[5];
    const float* b_out = (const float*)d_in[6];
    float* out = (float*)d_out;

    dim3 grid(16384 / ROWS_PER_CTA);   // 256 CTAs x 4 warps = 1024 warps
    dim3 blk(128);                     // wid 0..3 -> all four SMSPs
    rnn_mma_kernel<<<grid, blk>>>(x, Wxh, b_xh, Whh, b_hh, Wout, b_out, out);
}